// round 5
// baseline (speedup 1.0000x reference)
#include <cuda_runtime.h>
#include <math.h>
#include <stdint.h>

// Problem constants
#define Bn    128
#define Sn    256
#define Dn    256
#define Hn    6
#define HSn   42
#define HC    252        // Hn*HSn
#define NQKVP 768        // 3*HC = 756, padded to 768 for tile-exact GEMM
#define DFFn  1024
#define Mrows 32768      // Bn*Sn
#define BHn   (Bn*Hn)    // 768

// ---------------------------------------------------------------------------
// Scratch (allocation-free: __device__ globals)
// ---------------------------------------------------------------------------
__device__ float  g_qkv  [(size_t)Mrows * NQKVP];  // [M, 768] q|k|v head-concat
__device__ float  g_heads[(size_t)Mrows * Dn];     // [M, 256] head_cat (cols 252..255 = 0)
__device__ float  g_res1 [(size_t)Mrows * Dn];
__device__ float  g_ln1  [(size_t)Mrows * Dn];
__device__ float  g_ff1  [(size_t)Mrows * DFFn];
__device__ float  g_res2 [(size_t)Mrows * Dn];
__device__ float  g_wqkv [Dn * NQKVP];
__device__ float  g_wproj[Dn * Dn];

// ---------------------------------------------------------------------------
// tf32 helpers
// ---------------------------------------------------------------------------
__device__ __forceinline__ uint32_t f2tf(float f) {
    uint32_t u;
    asm("cvt.rna.tf32.f32 %0, %1;" : "=r"(u) : "f"(f));
    return u;
}
__device__ __forceinline__ void mma_tf32(float c[4], const uint32_t a[4], const uint32_t b[2]) {
    asm volatile(
        "mma.sync.aligned.m16n8k8.row.col.f32.tf32.tf32.f32 "
        "{%0,%1,%2,%3}, {%4,%5,%6,%7}, {%8,%9}, {%0,%1,%2,%3};"
        : "+f"(c[0]), "+f"(c[1]), "+f"(c[2]), "+f"(c[3])
        : "r"(a[0]), "r"(a[1]), "r"(a[2]), "r"(a[3]), "r"(b[0]), "r"(b[1]));
}

// ---------------------------------------------------------------------------
// Weight packing + zero g_heads pad columns
// ---------------------------------------------------------------------------
__global__ void pack_kernel(const float* __restrict__ Wq, const float* __restrict__ Wk,
                            const float* __restrict__ Wv, const float* __restrict__ Wproj,
                            float* __restrict__ wqkv, float* __restrict__ wproj_p,
                            float* __restrict__ heads) {
    int idx = blockIdx.x * 256 + threadIdx.x;
    if (idx < Dn * NQKVP) {
        int d = idx / NQKVP, j = idx % NQKVP;
        float val = 0.0f;
        if (j < 756) {
            int which = j / HC;
            int rr = j - which * HC;
            int h = rr / HSn, c = rr - h * HSn;
            const float* W = (which == 0) ? Wq : (which == 1) ? Wk : Wv;
            val = W[(h * Dn + d) * HSn + c];
        }
        wqkv[idx] = val;
    }
    if (idx < Dn * Dn) {
        int rr = idx / Dn, c = idx % Dn;
        wproj_p[idx] = (rr < HC) ? Wproj[rr * Dn + c] : 0.0f;
    }
    if (idx < Mrows)   // zero head_cat pad cols 252..255
        *(float4*)&heads[(size_t)idx * Dn + 252] = make_float4(0.f, 0.f, 0.f, 0.f);
}

// ---------------------------------------------------------------------------
// tf32 tensor-core GEMM: C[M,N] = A[M,K] @ B[K,N] (+ epilogue)  (unchanged)
// ---------------------------------------------------------------------------
#define LDA 20
#define LDB 72

template<int MODE>
__global__ __launch_bounds__(256) void gemm_tc(
    const float* __restrict__ A, const float* __restrict__ B, float* __restrict__ C,
    const float* __restrict__ bias, const float* __restrict__ resid,
    int M, int N, int K)
{
    __shared__ uint32_t As[2][128 * LDA];
    __shared__ uint32_t Bs[2][16 * LDB];

    int tid  = threadIdx.x;
    int lane = tid & 31, wid = tid >> 5;
    int wm = wid & 3, wn = wid >> 2;
    int bm = blockIdx.y * 128, bn = blockIdx.x * 64;
    int r  = lane >> 2, cq = lane & 3;

    float acc[2][4][4];
#pragma unroll
    for (int mf = 0; mf < 2; mf++)
#pragma unroll
        for (int nf = 0; nf < 4; nf++)
#pragma unroll
            for (int i = 0; i < 4; i++) acc[mf][nf][i] = 0.0f;

    int a_r = tid >> 2;
    int a_c = (tid & 3) << 2;
    int b_r = tid >> 4;
    int b_c = (tid & 15) << 2;

    const float* Ag0 = A + (size_t)(bm + a_r) * K + a_c;
    const float* Ag1 = A + (size_t)(bm + a_r + 64) * K + a_c;
    const float* Bg  = B + (size_t)b_r * N + bn + b_c;

    float4 ra0, ra1, rb;
    ra0 = *(const float4*)(Ag0);
    ra1 = *(const float4*)(Ag1);
    rb  = *(const float4*)(Bg);
    {
        uint4 u0 = make_uint4(f2tf(ra0.x), f2tf(ra0.y), f2tf(ra0.z), f2tf(ra0.w));
        uint4 u1 = make_uint4(f2tf(ra1.x), f2tf(ra1.y), f2tf(ra1.z), f2tf(ra1.w));
        uint4 ub = make_uint4(f2tf(rb.x),  f2tf(rb.y),  f2tf(rb.z),  f2tf(rb.w));
        *(uint4*)&As[0][a_r * LDA + a_c]        = u0;
        *(uint4*)&As[0][(a_r + 64) * LDA + a_c] = u1;
        *(uint4*)&Bs[0][b_r * LDB + b_c]        = ub;
    }
    __syncthreads();

    int nk = K >> 4;
    for (int it = 0; it < nk; it++) {
        int cur = it & 1, nxt = cur ^ 1;
        bool more = (it + 1 < nk);
        if (more) {
            int k0 = (it + 1) << 4;
            ra0 = *(const float4*)(Ag0 + k0);
            ra1 = *(const float4*)(Ag1 + k0);
            rb  = *(const float4*)(Bg + (size_t)k0 * N);
        }
#pragma unroll
        for (int kk = 0; kk < 16; kk += 8) {
            uint32_t a[2][4], b[4][2];
#pragma unroll
            for (int mf = 0; mf < 2; mf++) {
                int ar = (wm * 32 + mf * 16 + r) * LDA + kk + cq;
                a[mf][0] = As[cur][ar];
                a[mf][1] = As[cur][ar + 8 * LDA];
                a[mf][2] = As[cur][ar + 4];
                a[mf][3] = As[cur][ar + 8 * LDA + 4];
            }
#pragma unroll
            for (int nf = 0; nf < 4; nf++) {
                int bc = (kk + cq) * LDB + wn * 32 + nf * 8 + r;
                b[nf][0] = Bs[cur][bc];
                b[nf][1] = Bs[cur][bc + 4 * LDB];
            }
#pragma unroll
            for (int mf = 0; mf < 2; mf++)
#pragma unroll
                for (int nf = 0; nf < 4; nf++)
                    mma_tf32(acc[mf][nf], a[mf], b[nf]);
        }
        if (more) {
            uint4 u0 = make_uint4(f2tf(ra0.x), f2tf(ra0.y), f2tf(ra0.z), f2tf(ra0.w));
            uint4 u1 = make_uint4(f2tf(ra1.x), f2tf(ra1.y), f2tf(ra1.z), f2tf(ra1.w));
            uint4 ub = make_uint4(f2tf(rb.x),  f2tf(rb.y),  f2tf(rb.z),  f2tf(rb.w));
            *(uint4*)&As[nxt][a_r * LDA + a_c]        = u0;
            *(uint4*)&As[nxt][(a_r + 64) * LDA + a_c] = u1;
            *(uint4*)&Bs[nxt][b_r * LDB + b_c]        = ub;
        }
        __syncthreads();
    }

#pragma unroll
    for (int mf = 0; mf < 2; mf++) {
#pragma unroll
        for (int nf = 0; nf < 4; nf++) {
            int row = bm + wm * 32 + mf * 16 + r;
            int col = bn + wn * 32 + nf * 8 + cq * 2;
            float v0 = acc[mf][nf][0], v1 = acc[mf][nf][1];
            float v2 = acc[mf][nf][2], v3 = acc[mf][nf][3];
            size_t o0 = (size_t)row * N + col;
            size_t o1 = (size_t)(row + 8) * N + col;
            if (MODE == 1) {
                float b0 = bias[col], b1 = bias[col + 1];
                v0 = fmaxf(v0 + b0, 0.f); v1 = fmaxf(v1 + b1, 0.f);
                v2 = fmaxf(v2 + b0, 0.f); v3 = fmaxf(v3 + b1, 0.f);
            }
            if (MODE == 2) {
                float b0 = bias[col], b1 = bias[col + 1];
                float2 r0 = *(const float2*)(resid + o0);
                float2 r1 = *(const float2*)(resid + o1);
                v0 += b0 + r0.x; v1 += b1 + r0.y;
                v2 += b0 + r1.x; v3 += b1 + r1.y;
            }
            *(float2*)(C + o0) = make_float2(v0, v1);
            *(float2*)(C + o1) = make_float2(v2, v3);
        }
    }
}

// ---------------------------------------------------------------------------
// Fused causal attention: one block per (b, h, mtile). 256 threads, 8 warps.
// All of Q-tile / K / V-chunk / P live in SMEM; P never touches DRAM.
// Softmax via Cauchy-Schwarz bound m0 (no row max, no rescale).
//   Phase A: load Q(scaled, tf32), K(all keys this tile needs), compute m0.
//   Per 128-key chunk: S=QK^T (MMA, warp 32x64) -> p=exp(s-m0) + causal mask
//     -> rowsum atomics -> P to smem (tf32) ; V chunk load ; O += P@V (MMA,
//     warp 16x48).
//   Epilogue: O/l -> g_heads.
// ---------------------------------------------------------------------------
#define LQ  52    // Q/K smem pitch (48 + 4)
#define LVF 56    // V smem pitch
#define LP  132   // P smem pitch (128 + 4)
#define ATTN_SMEM ((128*LQ + 256*LQ + 128*LVF + 128*LP) * 4 + (128 + 128 + 8) * 4)

__global__ __launch_bounds__(256) void attn_fused(const float* __restrict__ qkv,
                                                  float* __restrict__ heads) {
    extern __shared__ uint32_t smu[];
    uint32_t* Qs = smu;                    // [128][LQ]
    uint32_t* Ks = Qs + 128 * LQ;          // [256][LQ]
    uint32_t* Vs = Ks + 256 * LQ;          // [128][LVF]
    uint32_t* Ps = Vs + 128 * LVF;         // [128][LP]
    float* lrow = (float*)(Ps + 128 * LP); // [128]
    float* m0s  = lrow + 128;              // [128]
    float* red  = m0s + 128;               // [8]

    int bh = blockIdx.x;
    int b = bh / Hn, h = bh - b * Hn;
    int mtile = blockIdx.y;
    int bm = mtile * 128;
    int nkeys = bm + 128;

    int tid = threadIdx.x, lane = tid & 31, wid = tid >> 5;
    int r = lane >> 2, cq = lane & 3;
    const float scale = rsqrtf(42.0f);
    const float* base = qkv + (size_t)b * Sn * NQKVP;

    // ---- Phase A: load Q (scaled) and all K rows this tile attends ----
    for (int idx = tid; idx < 128 * 48; idx += 256) {
        int rr = idx / 48, c = idx - rr * 48;
        float v = (c < HSn) ? base[(size_t)(bm + rr) * NQKVP + h * HSn + c] * scale : 0.f;
        Qs[rr * LQ + c] = f2tf(v);
    }
    for (int idx = tid; idx < nkeys * 48; idx += 256) {
        int rr = idx / 48, c = idx - rr * 48;
        float v = (c < HSn) ? base[(size_t)rr * NQKVP + HC + h * HSn + c] : 0.f;
        Ks[rr * LQ + c] = f2tf(v);
    }
    if (tid < 128) lrow[tid] = 0.f;
    __syncthreads();

    // kmax2 = max over K rows of |k|^2 (on the tf32 values actually used)
    float kn = 0.f;
    for (int rr = tid; rr < nkeys; rr += 256) {
        float s = 0.f;
#pragma unroll
        for (int c = 0; c < HSn; c++) {
            float v = __uint_as_float(Ks[rr * LQ + c]);
            s = fmaf(v, v, s);
        }
        kn = fmaxf(kn, s);
    }
#pragma unroll
    for (int off = 16; off > 0; off >>= 1)
        kn = fmaxf(kn, __shfl_xor_sync(0xffffffffu, kn, off));
    if (lane == 0) red[wid] = kn;
    __syncthreads();
    float kmax2 = fmaxf(fmaxf(fmaxf(red[0], red[1]), fmaxf(red[2], red[3])),
                        fmaxf(fmaxf(red[4], red[5]), fmaxf(red[6], red[7])));
    if (tid < 128) {
        float qn = 0.f;
#pragma unroll
        for (int c = 0; c < HSn; c++) {
            float v = __uint_as_float(Qs[tid * LQ + c]);
            qn = fmaf(v, v, qn);
        }
        m0s[tid] = sqrtf(qn * kmax2);   // >= all scores of this row
    }

    float oacc[6][4];
#pragma unroll
    for (int nf = 0; nf < 6; nf++)
#pragma unroll
        for (int i = 0; i < 4; i++) oacc[nf][i] = 0.f;

    // S-phase warp coords: 4m x 2n, warp tile 32 x 64
    int wm = wid & 3, wn = wid >> 2;

    for (int kc = 0; kc <= mtile; kc++) {
        __syncthreads();   // prev chunk's PV done; Vs/Ps reusable; m0s ready (kc=0)

        // load V chunk (tf32)
        for (int idx = tid; idx < 128 * 48; idx += 256) {
            int rr = idx / 48, c = idx - rr * 48;
            float v = (c < HSn)
                ? base[(size_t)(kc * 128 + rr) * NQKVP + 2 * HC + h * HSn + c] : 0.f;
            Vs[rr * LVF + c] = f2tf(v);
        }

        // S = Q @ K_chunk^T
        float sacc[2][8][4];
#pragma unroll
        for (int mf = 0; mf < 2; mf++)
#pragma unroll
            for (int nf = 0; nf < 8; nf++)
#pragma unroll
                for (int i = 0; i < 4; i++) sacc[mf][nf][i] = 0.f;

#pragma unroll
        for (int kk = 0; kk < 48; kk += 8) {
            uint32_t a[2][4], bf[8][2];
#pragma unroll
            for (int mf = 0; mf < 2; mf++) {
                int ar = (wm * 32 + mf * 16 + r) * LQ + kk + cq;
                a[mf][0] = Qs[ar];
                a[mf][1] = Qs[ar + 8 * LQ];
                a[mf][2] = Qs[ar + 4];
                a[mf][3] = Qs[ar + 8 * LQ + 4];
            }
#pragma unroll
            for (int nf = 0; nf < 8; nf++) {
                int bc = (kc * 128 + wn * 64 + nf * 8 + r) * LQ + kk + cq;
                bf[nf][0] = Ks[bc];
                bf[nf][1] = Ks[bc + 4];
            }
#pragma unroll
            for (int mf = 0; mf < 2; mf++)
#pragma unroll
                for (int nf = 0; nf < 8; nf++)
                    mma_tf32(sacc[mf][nf], a[mf], bf[nf]);
        }

        // p = exp(s - m0) with causal mask; row sums; store tf32 P to smem
#pragma unroll
        for (int mf = 0; mf < 2; mf++) {
            int lr0 = wm * 32 + mf * 16 + r;          // local rows
            int lr1 = lr0 + 8;
            int gr0 = bm + lr0, gr1 = bm + lr1;       // global rows
            float m00 = m0s[lr0], m01 = m0s[lr1];
            float rs0 = 0.f, rs1 = 0.f;
#pragma unroll
            for (int nf = 0; nf < 8; nf++) {
                int lc = wn * 64 + nf * 8 + cq * 2;   // local col in chunk
                int gc = kc * 128 + lc;               // global key index
                float p00 = (gc     <= gr0) ? __expf(sacc[mf][nf][0] - m00) : 0.f;
                float p01 = (gc + 1 <= gr0) ? __expf(sacc[mf][nf][1] - m00) : 0.f;
                float p10 = (gc     <= gr1) ? __expf(sacc[mf][nf][2] - m01) : 0.f;
                float p11 = (gc + 1 <= gr1) ? __expf(sacc[mf][nf][3] - m01) : 0.f;
                rs0 += p00 + p01;
                rs1 += p10 + p11;
                *(uint2*)&Ps[lr0 * LP + lc] = make_uint2(f2tf(p00), f2tf(p01));
                *(uint2*)&Ps[lr1 * LP + lc] = make_uint2(f2tf(p10), f2tf(p11));
            }
            rs0 += __shfl_xor_sync(0xffffffffu, rs0, 1);
            rs0 += __shfl_xor_sync(0xffffffffu, rs0, 2);
            rs1 += __shfl_xor_sync(0xffffffffu, rs1, 1);
            rs1 += __shfl_xor_sync(0xffffffffu, rs1, 2);
            if (cq == 0) {
                atomicAdd(&lrow[lr0], rs0);
                atomicAdd(&lrow[lr1], rs1);
            }
        }
        __syncthreads();   // P + V visible

        // O += P @ V_chunk : warp tile 16 rows x 48 cols
#pragma unroll
        for (int kk = 0; kk < 128; kk += 8) {
            uint32_t a[4];
            int ar = (wid * 16 + r) * LP + kk + cq;
            a[0] = Ps[ar];
            a[1] = Ps[ar + 8 * LP];
            a[2] = Ps[ar + 4];
            a[3] = Ps[ar + 8 * LP + 4];
            uint32_t bf[6][2];
#pragma unroll
            for (int nf = 0; nf < 6; nf++) {
                int bc = (kk + cq) * LVF + nf * 8 + r;
                bf[nf][0] = Vs[bc];
                bf[nf][1] = Vs[bc + 4 * LVF];
            }
#pragma unroll
            for (int nf = 0; nf < 6; nf++)
                mma_tf32(oacc[nf], a, bf[nf]);
        }
    }
    __syncthreads();

    // epilogue: divide by row sums, write to head_cat
    int lr0 = wid * 16 + r;
    int lr1 = lr0 + 8;
    float li0 = 1.0f / lrow[lr0];
    float li1 = 1.0f / lrow[lr1];
#pragma unroll
    for (int nf = 0; nf < 6; nf++) {
        int col = nf * 8 + cq * 2;
        if (col < HSn) {
            *(float2*)&heads[(size_t)(b * Sn + bm + lr0) * Dn + h * HSn + col] =
                make_float2(oacc[nf][0] * li0, oacc[nf][1] * li0);
            *(float2*)&heads[(size_t)(b * Sn + bm + lr1) * Dn + h * HSn + col] =
                make_float2(oacc[nf][2] * li1, oacc[nf][3] * li1);
        }
    }
}

// ---------------------------------------------------------------------------
// LayerNorm over last dim (256): one warp per row.
// ---------------------------------------------------------------------------
__global__ void ln_kernel(const float* __restrict__ in, const float* __restrict__ g,
                          const float* __restrict__ bb, float* __restrict__ out) {
    int row = blockIdx.x * blockDim.y + threadIdx.y;
    int lane = threadIdx.x;
    const float4* x = (const float4*)(in + (size_t)row * Dn);
    float4 a = x[lane];
    float4 c = x[lane + 32];
    float s  = a.x + a.y + a.z + a.w + c.x + c.y + c.z + c.w;
    float ss = a.x*a.x + a.y*a.y + a.z*a.z + a.w*a.w
             + c.x*c.x + c.y*c.y + c.z*c.z + c.w*c.w;
#pragma unroll
    for (int off = 16; off > 0; off >>= 1) {
        s  += __shfl_xor_sync(0xffffffffu, s,  off);
        ss += __shfl_xor_sync(0xffffffffu, ss, off);
    }
    float mean = s * (1.0f / 256.0f);
    float var  = ss * (1.0f / 256.0f) - mean * mean;
    float rstd = rsqrtf(var + 1e-5f);
    float4 g1 = ((const float4*)g)[lane],  g2 = ((const float4*)g)[lane + 32];
    float4 b1 = ((const float4*)bb)[lane], b2 = ((const float4*)bb)[lane + 32];
    float4 r1, r2;
    r1.x = (a.x - mean) * rstd * g1.x + b1.x;
    r1.y = (a.y - mean) * rstd * g1.y + b1.y;
    r1.z = (a.z - mean) * rstd * g1.z + b1.z;
    r1.w = (a.w - mean) * rstd * g1.w + b1.w;
    r2.x = (c.x - mean) * rstd * g2.x + b2.x;
    r2.y = (c.y - mean) * rstd * g2.y + b2.y;
    r2.z = (c.z - mean) * rstd * g2.z + b2.z;
    r2.w = (c.w - mean) * rstd * g2.w + b2.w;
    float4* o4 = (float4*)(out + (size_t)row * Dn);
    o4[lane] = r1;
    o4[lane + 32] = r2;
}

// ---------------------------------------------------------------------------
// Launch
// ---------------------------------------------------------------------------
extern "C" void kernel_launch(void* const* d_in, const int* in_sizes, int n_in,
                              void* d_out, int out_size) {
    const float* x     = (const float*)d_in[0];
    const float* Wq    = (const float*)d_in[1];
    const float* Wk    = (const float*)d_in[2];
    const float* Wv    = (const float*)d_in[3];
    const float* Wproj = (const float*)d_in[4];
    const float* bproj = (const float*)d_in[5];
    const float* ln1_g = (const float*)d_in[6];
    const float* ln1_b = (const float*)d_in[7];
    const float* W1    = (const float*)d_in[8];
    const float* b1    = (const float*)d_in[9];
    const float* W2    = (const float*)d_in[10];
    const float* b2    = (const float*)d_in[11];
    const float* ln2_g = (const float*)d_in[12];
    const float* ln2_b = (const float*)d_in[13];
    float* out = (float*)d_out;

    float *qkv, *heads, *res1, *ln1, *ff1, *res2, *wqkv, *wproj;
    cudaGetSymbolAddress((void**)&qkv,   g_qkv);
    cudaGetSymbolAddress((void**)&heads, g_heads);
    cudaGetSymbolAddress((void**)&res1,  g_res1);
    cudaGetSymbolAddress((void**)&ln1,   g_ln1);
    cudaGetSymbolAddress((void**)&ff1,   g_ff1);
    cudaGetSymbolAddress((void**)&res2,  g_res2);
    cudaGetSymbolAddress((void**)&wqkv,  g_wqkv);
    cudaGetSymbolAddress((void**)&wproj, g_wproj);

    cudaFuncSetAttribute(attn_fused, cudaFuncAttributeMaxDynamicSharedMemorySize, ATTN_SMEM);

    // 1. pack weights (+ zero head_cat pad cols)
    pack_kernel<<<768, 256>>>(Wq, Wk, Wv, Wproj, wqkv, wproj, heads);
    // 2. QKV:   [32768,256] @ [256,768]
    gemm_tc<0><<<dim3(NQKVP / 64, Mrows / 128), 256>>>(x, wqkv, qkv, nullptr, nullptr, Mrows, NQKVP, Dn);
    // 3. fused attention -> head_cat
    attn_fused<<<dim3(BHn, 2), 256, ATTN_SMEM>>>(qkv, heads);
    // 4. proj + residual(x)
    gemm_tc<2><<<dim3(Dn / 64, Mrows / 128), 256>>>(heads, wproj, res1, bproj, x, Mrows, Dn, Dn);
    // 5. LN1
    ln_kernel<<<Mrows / 8, dim3(32, 8)>>>(res1, ln1_g, ln1_b, ln1);
    // 6. FFN1 + ReLU
    gemm_tc<1><<<dim3(DFFn / 64, Mrows / 128), 256>>>(ln1, W1, ff1, b1, nullptr, Mrows, DFFn, Dn);
    // 7. FFN2 + residual(ln1)
    gemm_tc<2><<<dim3(Dn / 64, Mrows / 128), 256>>>(ff1, W2, res2, b2, ln1, Mrows, Dn, DFFn);
    // 8. LN2 -> output
    ln_kernel<<<Mrows / 8, dim3(32, 8)>>>(res2, ln2_g, ln2_b, out);
}

// round 7
// speedup vs baseline: 1.1880x; 1.1880x over previous
#include <cuda_runtime.h>
#include <math.h>
#include <stdint.h>

// Problem constants
#define Bn    128
#define Sn    256
#define Dn    256
#define Hn    6
#define HSn   42
#define HC    252        // Hn*HSn
#define NQKVP 768        // 3*HC = 756, padded to 768 for tile-exact GEMM
#define DFFn  1024
#define Mrows 32768      // Bn*Sn
#define BHn   (Bn*Hn)    // 768

// ---------------------------------------------------------------------------
// Scratch (allocation-free: __device__ globals)
// ---------------------------------------------------------------------------
__device__ float  g_qkv  [(size_t)Mrows * NQKVP];
__device__ float  g_heads[(size_t)Mrows * Dn];     // head_cat (cols 252..255 = 0)
__device__ float  g_res1 [(size_t)Mrows * Dn];
__device__ float  g_ln1  [(size_t)Mrows * Dn];
__device__ float  g_ff1  [(size_t)Mrows * DFFn];
__device__ float  g_res2 [(size_t)Mrows * Dn];
__device__ float  g_wqkv [Dn * NQKVP];
__device__ float  g_wproj[Dn * Dn];

// ---------------------------------------------------------------------------
// tf32 helpers
// ---------------------------------------------------------------------------
__device__ __forceinline__ uint32_t f2tf(float f) {
    uint32_t u;
    asm("cvt.rna.tf32.f32 %0, %1;" : "=r"(u) : "f"(f));
    return u;
}
__device__ __forceinline__ void mma_tf32(float c[4], const uint32_t a[4], const uint32_t b[2]) {
    asm volatile(
        "mma.sync.aligned.m16n8k8.row.col.f32.tf32.tf32.f32 "
        "{%0,%1,%2,%3}, {%4,%5,%6,%7}, {%8,%9}, {%0,%1,%2,%3};"
        : "+f"(c[0]), "+f"(c[1]), "+f"(c[2]), "+f"(c[3])
        : "r"(a[0]), "r"(a[1]), "r"(a[2]), "r"(a[3]), "r"(b[0]), "r"(b[1]));
}

// ---------------------------------------------------------------------------
// Weight packing + zero g_heads pad columns
// ---------------------------------------------------------------------------
__global__ void pack_kernel(const float* __restrict__ Wq, const float* __restrict__ Wk,
                            const float* __restrict__ Wv, const float* __restrict__ Wproj,
                            float* __restrict__ wqkv, float* __restrict__ wproj_p,
                            float* __restrict__ heads) {
    int idx = blockIdx.x * 256 + threadIdx.x;
    if (idx < Dn * NQKVP) {
        int d = idx / NQKVP, j = idx % NQKVP;
        float val = 0.0f;
        if (j < 756) {
            int which = j / HC;
            int rr = j - which * HC;
            int h = rr / HSn, c = rr - h * HSn;
            const float* W = (which == 0) ? Wq : (which == 1) ? Wk : Wv;
            val = W[(h * Dn + d) * HSn + c];
        }
        wqkv[idx] = val;
    }
    if (idx < Dn * Dn) {
        int rr = idx / Dn, c = idx % Dn;
        wproj_p[idx] = (rr < HC) ? Wproj[rr * Dn + c] : 0.0f;
    }
    if (idx < Mrows)
        *(float4*)&heads[(size_t)idx * Dn + 252] = make_float4(0.f, 0.f, 0.f, 0.f);
}

// ---------------------------------------------------------------------------
// tf32 tensor-core GEMM v2: C[M,N] = A[M,K] @ B[K,N] (+ epilogue)
// BM=128, BN=128, BK=16; 256 threads = 8 warps (2m x 4n), warp tile 64x32.
// Requires M%128==0, N%128==0, K%16==0 (true at all call sites).
// MODE 0: raw; MODE 1: relu(acc+bias); MODE 2: acc+bias+resid
// ---------------------------------------------------------------------------
#define LDA 20    // A smem pitch (16 + 4)
#define LDB 136   // B smem pitch (128 + 8)

template<int MODE>
__global__ __launch_bounds__(256) void gemm_tc(
    const float* __restrict__ A, const float* __restrict__ B, float* __restrict__ C,
    const float* __restrict__ bias, const float* __restrict__ resid,
    int M, int N, int K)
{
    __shared__ uint32_t As[2][128 * LDA];
    __shared__ uint32_t Bs[2][16 * LDB];

    int tid  = threadIdx.x;
    int lane = tid & 31, wid = tid >> 5;
    int wm = wid & 1, wn = wid >> 1;          // 2m x 4n warps
    int bm = blockIdx.y * 128, bn = blockIdx.x * 128;
    int r  = lane >> 2, cq = lane & 3;

    float acc[4][4][4];
#pragma unroll
    for (int mf = 0; mf < 4; mf++)
#pragma unroll
        for (int nf = 0; nf < 4; nf++)
#pragma unroll
            for (int i = 0; i < 4; i++) acc[mf][nf][i] = 0.0f;

    // load coords
    int a_r = tid >> 2;                 // 0..63 (+64)
    int a_c = (tid & 3) << 2;           // 0,4,8,12
    int b_r0 = tid >> 5;                // 0..7
    int b_r1 = b_r0 + 8;                // 8..15
    int b_c = (tid & 31) << 2;          // 0..124

    const float* Ag0 = A + (size_t)(bm + a_r) * K + a_c;
    const float* Ag1 = A + (size_t)(bm + a_r + 64) * K + a_c;
    const float* Bg0 = B + (size_t)b_r0 * N + bn + b_c;
    const float* Bg1 = B + (size_t)b_r1 * N + bn + b_c;

    float4 ra0, ra1, rb0, rb1;
    ra0 = *(const float4*)(Ag0);
    ra1 = *(const float4*)(Ag1);
    rb0 = *(const float4*)(Bg0);
    rb1 = *(const float4*)(Bg1);
    {
        uint4 u0 = make_uint4(f2tf(ra0.x), f2tf(ra0.y), f2tf(ra0.z), f2tf(ra0.w));
        uint4 u1 = make_uint4(f2tf(ra1.x), f2tf(ra1.y), f2tf(ra1.z), f2tf(ra1.w));
        uint4 v0 = make_uint4(f2tf(rb0.x), f2tf(rb0.y), f2tf(rb0.z), f2tf(rb0.w));
        uint4 v1 = make_uint4(f2tf(rb1.x), f2tf(rb1.y), f2tf(rb1.z), f2tf(rb1.w));
        *(uint4*)&As[0][a_r * LDA + a_c]        = u0;
        *(uint4*)&As[0][(a_r + 64) * LDA + a_c] = u1;
        *(uint4*)&Bs[0][b_r0 * LDB + b_c]       = v0;
        *(uint4*)&Bs[0][b_r1 * LDB + b_c]       = v1;
    }
    __syncthreads();

    int nk = K >> 4;
    for (int it = 0; it < nk; it++) {
        int cur = it & 1, nxt = cur ^ 1;
        bool more = (it + 1 < nk);
        if (more) {
            int k0 = (it + 1) << 4;
            ra0 = *(const float4*)(Ag0 + k0);
            ra1 = *(const float4*)(Ag1 + k0);
            rb0 = *(const float4*)(Bg0 + (size_t)k0 * N);
            rb1 = *(const float4*)(Bg1 + (size_t)k0 * N);
        }
#pragma unroll
        for (int kk = 0; kk < 16; kk += 8) {
            uint32_t a[4][4], b[4][2];
#pragma unroll
            for (int mf = 0; mf < 4; mf++) {
                int ar = (wm * 64 + mf * 16 + r) * LDA + kk + cq;
                a[mf][0] = As[cur][ar];
                a[mf][1] = As[cur][ar + 8 * LDA];
                a[mf][2] = As[cur][ar + 4];
                a[mf][3] = As[cur][ar + 8 * LDA + 4];
            }
#pragma unroll
            for (int nf = 0; nf < 4; nf++) {
                int bc = (kk + cq) * LDB + wn * 32 + nf * 8 + r;
                b[nf][0] = Bs[cur][bc];
                b[nf][1] = Bs[cur][bc + 4 * LDB];
            }
#pragma unroll
            for (int mf = 0; mf < 4; mf++)
#pragma unroll
                for (int nf = 0; nf < 4; nf++)
                    mma_tf32(acc[mf][nf], a[mf], b[nf]);
        }
        if (more) {
            uint4 u0 = make_uint4(f2tf(ra0.x), f2tf(ra0.y), f2tf(ra0.z), f2tf(ra0.w));
            uint4 u1 = make_uint4(f2tf(ra1.x), f2tf(ra1.y), f2tf(ra1.z), f2tf(ra1.w));
            uint4 v0 = make_uint4(f2tf(rb0.x), f2tf(rb0.y), f2tf(rb0.z), f2tf(rb0.w));
            uint4 v1 = make_uint4(f2tf(rb1.x), f2tf(rb1.y), f2tf(rb1.z), f2tf(rb1.w));
            *(uint4*)&As[nxt][a_r * LDA + a_c]        = u0;
            *(uint4*)&As[nxt][(a_r + 64) * LDA + a_c] = u1;
            *(uint4*)&Bs[nxt][b_r0 * LDB + b_c]       = v0;
            *(uint4*)&Bs[nxt][b_r1 * LDB + b_c]       = v1;
        }
        __syncthreads();
    }

#pragma unroll
    for (int mf = 0; mf < 4; mf++) {
#pragma unroll
        for (int nf = 0; nf < 4; nf++) {
            int row = bm + wm * 64 + mf * 16 + r;
            int col = bn + wn * 32 + nf * 8 + cq * 2;
            float v0 = acc[mf][nf][0], v1 = acc[mf][nf][1];
            float v2 = acc[mf][nf][2], v3 = acc[mf][nf][3];
            size_t o0 = (size_t)row * N + col;
            size_t o1 = (size_t)(row + 8) * N + col;
            if (MODE == 1) {
                float b0 = bias[col], b1 = bias[col + 1];
                v0 = fmaxf(v0 + b0, 0.f); v1 = fmaxf(v1 + b1, 0.f);
                v2 = fmaxf(v2 + b0, 0.f); v3 = fmaxf(v3 + b1, 0.f);
            }
            if (MODE == 2) {
                float b0 = bias[col], b1 = bias[col + 1];
                float2 r0 = *(const float2*)(resid + o0);
                float2 r1 = *(const float2*)(resid + o1);
                v0 += b0 + r0.x; v1 += b1 + r0.y;
                v2 += b0 + r1.x; v3 += b1 + r1.y;
            }
            *(float2*)(C + o0) = make_float2(v0, v1);
            *(float2*)(C + o1) = make_float2(v2, v3);
        }
    }
}

// ---------------------------------------------------------------------------
// Fused causal attention v2: one block per (b, h, mtile). 512 threads / 16
// warps (was 8) — same 177KB smem, 1 CTA/SM, but 4 warps/SMSP for latency
// hiding. S-phase warp grid 4m x 4n (32x32); PV-phase 8 rows x 2 col-groups
// (16x24 per warp). Softmax via Cauchy-Schwarz bound m0.
// ---------------------------------------------------------------------------
#define LQ  52
#define LVF 56
#define LP  132
#define ATTN_SMEM ((128*LQ + 256*LQ + 128*LVF + 128*LP) * 4 + (128 + 128 + 16) * 4)

__global__ __launch_bounds__(512) void attn_fused(const float* __restrict__ qkv,
                                                  float* __restrict__ heads) {
    extern __shared__ uint32_t smu[];
    uint32_t* Qs = smu;                    // [128][LQ]
    uint32_t* Ks = Qs + 128 * LQ;          // [256][LQ]
    uint32_t* Vs = Ks + 256 * LQ;          // [128][LVF]
    uint32_t* Ps = Vs + 128 * LVF;         // [128][LP]
    float* lrow = (float*)(Ps + 128 * LP); // [128]
    float* m0s  = lrow + 128;              // [128]
    float* red  = m0s + 128;               // [16]

    int bh = blockIdx.x;
    int b = bh / Hn, h = bh - b * Hn;
    int mtile = blockIdx.y;
    int bm = mtile * 128;
    int nkeys = bm + 128;

    int tid = threadIdx.x, lane = tid & 31, wid = tid >> 5;
    int r = lane >> 2, cq = lane & 3;
    const float scale = rsqrtf(42.0f);
    const float* base = qkv + (size_t)b * Sn * NQKVP;

    // ---- Phase A: load Q (scaled) and K rows; compute m0 ----
    for (int idx = tid; idx < 128 * 48; idx += 512) {
        int rr = idx / 48, c = idx - rr * 48;
        float v = (c < HSn) ? base[(size_t)(bm + rr) * NQKVP + h * HSn + c] * scale : 0.f;
        Qs[rr * LQ + c] = f2tf(v);
    }
    for (int idx = tid; idx < nkeys * 48; idx += 512) {
        int rr = idx / 48, c = idx - rr * 48;
        float v = (c < HSn) ? base[(size_t)rr * NQKVP + HC + h * HSn + c] : 0.f;
        Ks[rr * LQ + c] = f2tf(v);
    }
    if (tid < 128) lrow[tid] = 0.f;
    __syncthreads();

    float kn = 0.f;
    for (int rr = tid; rr < nkeys; rr += 512) {
        float s = 0.f;
#pragma unroll
        for (int c = 0; c < HSn; c++) {
            float v = __uint_as_float(Ks[rr * LQ + c]);
            s = fmaf(v, v, s);
        }
        kn = fmaxf(kn, s);
    }
#pragma unroll
    for (int off = 16; off > 0; off >>= 1)
        kn = fmaxf(kn, __shfl_xor_sync(0xffffffffu, kn, off));
    if (lane == 0) red[wid] = kn;
    __syncthreads();
    float kmax2 = red[0];
#pragma unroll
    for (int i = 1; i < 16; i++) kmax2 = fmaxf(kmax2, red[i]);
    if (tid < 128) {
        float qn = 0.f;
#pragma unroll
        for (int c = 0; c < HSn; c++) {
            float v = __uint_as_float(Qs[tid * LQ + c]);
            qn = fmaf(v, v, qn);
        }
        m0s[tid] = sqrtf(qn * kmax2);   // >= all scores of this row
    }

    // PV accumulators: warp covers rows (wid&7)*16..+15, cols (wid>>3)*24..+23
    float oacc[3][4];
#pragma unroll
    for (int nf = 0; nf < 3; nf++)
#pragma unroll
        for (int i = 0; i < 4; i++) oacc[nf][i] = 0.f;

    int wm = wid & 3, wn = wid >> 2;       // S-phase: 4m x 4n
    int pm = wid & 7, pn = wid >> 3;       // PV-phase: 8 rows x 2 col-groups

    for (int kc = 0; kc <= mtile; kc++) {
        __syncthreads();   // Vs/Ps reusable; m0s ready (first iter)

        // load V chunk
        for (int idx = tid; idx < 128 * 48; idx += 512) {
            int rr = idx / 48, c = idx - rr * 48;
            float v = (c < HSn)
                ? base[(size_t)(kc * 128 + rr) * NQKVP + 2 * HC + h * HSn + c] : 0.f;
            Vs[rr * LVF + c] = f2tf(v);
        }

        // S = Q @ K_chunk^T   (warp tile 32 x 32)
        float sacc[2][4][4];
#pragma unroll
        for (int mf = 0; mf < 2; mf++)
#pragma unroll
            for (int nf = 0; nf < 4; nf++)
#pragma unroll
                for (int i = 0; i < 4; i++) sacc[mf][nf][i] = 0.f;

#pragma unroll
        for (int kk = 0; kk < 48; kk += 8) {
            uint32_t a[2][4], bf[4][2];
#pragma unroll
            for (int mf = 0; mf < 2; mf++) {
                int ar = (wm * 32 + mf * 16 + r) * LQ + kk + cq;
                a[mf][0] = Qs[ar];
                a[mf][1] = Qs[ar + 8 * LQ];
                a[mf][2] = Qs[ar + 4];
                a[mf][3] = Qs[ar + 8 * LQ + 4];
            }
#pragma unroll
            for (int nf = 0; nf < 4; nf++) {
                int bc = (kc * 128 + wn * 32 + nf * 8 + r) * LQ + kk + cq;
                bf[nf][0] = Ks[bc];
                bf[nf][1] = Ks[bc + 4];
            }
#pragma unroll
            for (int mf = 0; mf < 2; mf++)
#pragma unroll
                for (int nf = 0; nf < 4; nf++)
                    mma_tf32(sacc[mf][nf], a[mf], bf[nf]);
        }

        // p = exp(s - m0) + causal mask; row sums; P -> smem (tf32)
#pragma unroll
        for (int mf = 0; mf < 2; mf++) {
            int lr0 = wm * 32 + mf * 16 + r;
            int lr1 = lr0 + 8;
            int gr0 = bm + lr0, gr1 = bm + lr1;
            float m00 = m0s[lr0], m01 = m0s[lr1];
            float rs0 = 0.f, rs1 = 0.f;
#pragma unroll
            for (int nf = 0; nf < 4; nf++) {
                int lc = wn * 32 + nf * 8 + cq * 2;
                int gc = kc * 128 + lc;
                float p00 = (gc     <= gr0) ? __expf(sacc[mf][nf][0] - m00) : 0.f;
                float p01 = (gc + 1 <= gr0) ? __expf(sacc[mf][nf][1] - m00) : 0.f;
                float p10 = (gc     <= gr1) ? __expf(sacc[mf][nf][2] - m01) : 0.f;
                float p11 = (gc + 1 <= gr1) ? __expf(sacc[mf][nf][3] - m01) : 0.f;
                rs0 += p00 + p01;
                rs1 += p10 + p11;
                *(uint2*)&Ps[lr0 * LP + lc] = make_uint2(f2tf(p00), f2tf(p01));
                *(uint2*)&Ps[lr1 * LP + lc] = make_uint2(f2tf(p10), f2tf(p11));
            }
            rs0 += __shfl_xor_sync(0xffffffffu, rs0, 1);
            rs0 += __shfl_xor_sync(0xffffffffu, rs0, 2);
            rs1 += __shfl_xor_sync(0xffffffffu, rs1, 1);
            rs1 += __shfl_xor_sync(0xffffffffu, rs1, 2);
            if (cq == 0) {
                atomicAdd(&lrow[lr0], rs0);
                atomicAdd(&lrow[lr1], rs1);
            }
        }
        __syncthreads();   // P + V visible

        // O += P @ V_chunk : warp tile 16 rows x 24 cols
#pragma unroll
        for (int kk = 0; kk < 128; kk += 8) {
            uint32_t a[4];
            int ar = (pm * 16 + r) * LP + kk + cq;
            a[0] = Ps[ar];
            a[1] = Ps[ar + 8 * LP];
            a[2] = Ps[ar + 4];
            a[3] = Ps[ar + 8 * LP + 4];
            uint32_t bf[3][2];
#pragma unroll
            for (int nf = 0; nf < 3; nf++) {
                int bc = (kk + cq) * LVF + pn * 24 + nf * 8 + r;
                bf[nf][0] = Vs[bc];
                bf[nf][1] = Vs[bc + 4 * LVF];
            }
#pragma unroll
            for (int nf = 0; nf < 3; nf++)
                mma_tf32(oacc[nf], a, bf[nf]);
        }
    }
    __syncthreads();

    // epilogue: divide by row sums, write to head_cat
    int lr0 = pm * 16 + r;
    int lr1 = lr0 + 8;
    float li0 = 1.0f / lrow[lr0];
    float li1 = 1.0f / lrow[lr1];
#pragma unroll
    for (int nf = 0; nf < 3; nf++) {
        int col = pn * 24 + nf * 8 + cq * 2;
        if (col < HSn) {
            *(float2*)&heads[(size_t)(b * Sn + bm + lr0) * Dn + h * HSn + col] =
                make_float2(oacc[nf][0] * li0, oacc[nf][1] * li0);
            *(float2*)&heads[(size_t)(b * Sn + bm + lr1) * Dn + h * HSn + col] =
                make_float2(oacc[nf][2] * li1, oacc[nf][3] * li1);
        }
    }
}

// ---------------------------------------------------------------------------
// LayerNorm over last dim (256): one warp per row.
// ---------------------------------------------------------------------------
__global__ void ln_kernel(const float* __restrict__ in, const float* __restrict__ g,
                          const float* __restrict__ bb, float* __restrict__ out) {
    int row = blockIdx.x * blockDim.y + threadIdx.y;
    int lane = threadIdx.x;
    const float4* x = (const float4*)(in + (size_t)row * Dn);
    float4 a = x[lane];
    float4 c = x[lane + 32];
    float s  = a.x + a.y + a.z + a.w + c.x + c.y + c.z + c.w;
    float ss = a.x*a.x + a.y*a.y + a.z*a.z + a.w*a.w
             + c.x*c.x + c.y*c.y + c.z*c.z + c.w*c.w;
#pragma unroll
    for (int off = 16; off > 0; off >>= 1) {
        s  += __shfl_xor_sync(0xffffffffu, s,  off);
        ss += __shfl_xor_sync(0xffffffffu, ss, off);
    }
    float mean = s * (1.0f / 256.0f);
    float var  = ss * (1.0f / 256.0f) - mean * mean;
    float rstd = rsqrtf(var + 1e-5f);
    float4 g1 = ((const float4*)g)[lane],  g2 = ((const float4*)g)[lane + 32];
    float4 b1 = ((const float4*)bb)[lane], b2 = ((const float4*)bb)[lane + 32];
    float4 r1, r2;
    r1.x = (a.x - mean) * rstd * g1.x + b1.x;
    r1.y = (a.y - mean) * rstd * g1.y + b1.y;
    r1.z = (a.z - mean) * rstd * g1.z + b1.z;
    r1.w = (a.w - mean) * rstd * g1.w + b1.w;
    r2.x = (c.x - mean) * rstd * g2.x + b2.x;
    r2.y = (c.y - mean) * rstd * g2.y + b2.y;
    r2.z = (c.z - mean) * rstd * g2.z + b2.z;
    r2.w = (c.w - mean) * rstd * g2.w + b2.w;
    float4* o4 = (float4*)(out + (size_t)row * Dn);
    o4[lane] = r1;
    o4[lane + 32] = r2;
}

// ---------------------------------------------------------------------------
// Launch
// ---------------------------------------------------------------------------
extern "C" void kernel_launch(void* const* d_in, const int* in_sizes, int n_in,
                              void* d_out, int out_size) {
    const float* x     = (const float*)d_in[0];
    const float* Wq    = (const float*)d_in[1];
    const float* Wk    = (const float*)d_in[2];
    const float* Wv    = (const float*)d_in[3];
    const float* Wproj = (const float*)d_in[4];
    const float* bproj = (const float*)d_in[5];
    const float* ln1_g = (const float*)d_in[6];
    const float* ln1_b = (const float*)d_in[7];
    const float* W1    = (const float*)d_in[8];
    const float* b1    = (const float*)d_in[9];
    const float* W2    = (const float*)d_in[10];
    const float* b2    = (const float*)d_in[11];
    const float* ln2_g = (const float*)d_in[12];
    const float* ln2_b = (const float*)d_in[13];
    float* out = (float*)d_out;

    float *qkv, *heads, *res1, *ln1, *ff1, *res2, *wqkv, *wproj;
    cudaGetSymbolAddress((void**)&qkv,   g_qkv);
    cudaGetSymbolAddress((void**)&heads, g_heads);
    cudaGetSymbolAddress((void**)&res1,  g_res1);
    cudaGetSymbolAddress((void**)&ln1,   g_ln1);
    cudaGetSymbolAddress((void**)&ff1,   g_ff1);
    cudaGetSymbolAddress((void**)&res2,  g_res2);
    cudaGetSymbolAddress((void**)&wqkv,  g_wqkv);
    cudaGetSymbolAddress((void**)&wproj, g_wproj);

    cudaFuncSetAttribute(attn_fused, cudaFuncAttributeMaxDynamicSharedMemorySize, ATTN_SMEM);

    // 1. pack weights (+ zero head_cat pad cols)
    pack_kernel<<<768, 256>>>(Wq, Wk, Wv, Wproj, wqkv, wproj, heads);
    // 2. QKV:   [32768,256] @ [256,768]
    gemm_tc<0><<<dim3(NQKVP / 128, Mrows / 128), 256>>>(x, wqkv, qkv, nullptr, nullptr, Mrows, NQKVP, Dn);
    // 3. fused attention -> head_cat
    attn_fused<<<dim3(BHn, 2), 512, ATTN_SMEM>>>(qkv, heads);
    // 4. proj + residual(x)
    gemm_tc<2><<<dim3(Dn / 128, Mrows / 128), 256>>>(heads, wproj, res1, bproj, x, Mrows, Dn, Dn);
    // 5. LN1
    ln_kernel<<<Mrows / 8, dim3(32, 8)>>>(res1, ln1_g, ln1_b, ln1);
    // 6. FFN1 + ReLU
    gemm_tc<1><<<dim3(DFFn / 128, Mrows / 128), 256>>>(ln1, W1, ff1, b1, nullptr, Mrows, DFFn, Dn);
    // 7. FFN2 + residual(ln1)
    gemm_tc<2><<<dim3(Dn / 128, Mrows / 128), 256>>>(ff1, W2, res2, b2, ln1, Mrows, Dn, DFFn);
    // 8. LN2 -> output
    ln_kernel<<<Mrows / 8, dim3(32, 8)>>>(res2, ln2_g, ln2_b, out);
}